// round 2
// baseline (speedup 1.0000x reference)
#include <cuda_runtime.h>
#include <math.h>

#define BATCH 4
#define SEQ 2048
#define RTOT (BATCH*SEQ)        // 8192 rows
#define INPUT_LEN 15
#define D_MODEL 256
#define N_LAYERS 4
#define D_INNER 512
#define D_STATE 16
#define D_CONV 4
#define DT_RANK 16
#define XPROJ_N (DT_RANK + 2*D_STATE)   // 48
#define NC 32                   // chunks for parallel scan
#define CHUNK (SEQ/NC)          // 64
#define LN_EPS 1e-5f

// ---------------- persistent device scratch (no allocations) ----------------
__device__ float g_h  [RTOT*D_MODEL];
__device__ float g_res[RTOT*D_MODEL];
__device__ float g_hn [RTOT*D_MODEL];
__device__ float g_xz [RTOT*2*D_INNER];
__device__ float g_xh [RTOT*D_INNER];
__device__ float g_dbl[RTOT*XPROJ_N];
__device__ float g_dt [RTOT*D_INNER];
__device__ float g_y  [RTOT*D_INNER];
__device__ float g_cP   [BATCH*D_INNER*D_STATE*NC];
__device__ float g_cH   [BATCH*D_INNER*D_STATE*NC];
__device__ float g_carry[BATCH*D_INNER*D_STATE*NC];

// ---------------- embed: h = x_src @ in_W^T ----------------
__global__ void embed_kernel(const float* __restrict__ x, const float* __restrict__ W) {
    __shared__ float xs[INPUT_LEN];
    int r = blockIdx.x;
    int m = threadIdx.x;
    if (m < INPUT_LEN) xs[m] = x[r*INPUT_LEN + m];
    __syncthreads();
    float acc = 0.f;
#pragma unroll
    for (int k = 0; k < INPUT_LEN; k++) acc += xs[k] * W[m*INPUT_LEN + k];
    g_h[r*D_MODEL + m] = acc;
}

// ---------------- residual add + layernorm ----------------
__global__ void add_ln_kernel(const float* __restrict__ w, const float* __restrict__ b, int first) {
    int r = blockIdx.x;
    int c = threadIdx.x;
    float v = g_h[r*D_MODEL + c];
    if (!first) v += g_res[r*D_MODEL + c];
    g_res[r*D_MODEL + c] = v;

    float s = v, s2 = v*v;
#pragma unroll
    for (int o = 16; o > 0; o >>= 1) {
        s  += __shfl_xor_sync(0xffffffffu, s,  o);
        s2 += __shfl_xor_sync(0xffffffffu, s2, o);
    }
    __shared__ float ss[8], ss2[8];
    int wid = threadIdx.x >> 5, lane = threadIdx.x & 31;
    if (lane == 0) { ss[wid] = s; ss2[wid] = s2; }
    __syncthreads();
    if (wid == 0) {
        s  = (lane < 8) ? ss[lane]  : 0.f;
        s2 = (lane < 8) ? ss2[lane] : 0.f;
#pragma unroll
        for (int o = 4; o > 0; o >>= 1) {
            s  += __shfl_xor_sync(0xffffffffu, s,  o);
            s2 += __shfl_xor_sync(0xffffffffu, s2, o);
        }
        if (lane == 0) { ss[0] = s; ss2[0] = s2; }
    }
    __syncthreads();
    float mean = ss[0] * (1.0f/D_MODEL);
    float var  = ss2[0] * (1.0f/D_MODEL) - mean*mean;
    g_hn[r*D_MODEL + c] = (v - mean) * rsqrtf(var + LN_EPS) * w[c] + b[c];
}

// ---------------- tiled SGEMM: C[M,N] = A[M,K] @ W[N,K]^T ----------------
#define GBM 128
#define GBN 64
#define GBK 16
__global__ __launch_bounds__(256) void gemm_nt_kernel(
    const float* __restrict__ A, const float* __restrict__ W, float* __restrict__ C,
    int M, int N, int K)
{
    __shared__ float As[GBK][GBM];
    __shared__ float Ws[GBK][GBN];
    int tid = threadIdx.x;                 // 256 threads
    int m0 = blockIdx.y * GBM;
    int n0 = blockIdx.x * GBN;
    int ty = tid >> 4, tx = tid & 15;      // 16x16 thread grid; 8x4 micro tile

    float acc[8][4];
#pragma unroll
    for (int i = 0; i < 8; i++)
#pragma unroll
        for (int j = 0; j < 4; j++) acc[i][j] = 0.f;

    for (int k0 = 0; k0 < K; k0 += GBK) {
        // A tile: 128x16 = 512 float4, 2 per thread
#pragma unroll
        for (int it = 0; it < 2; it++) {
            int f = tid + it*256;
            int m = f >> 2, kq = f & 3;
            float4 v = *reinterpret_cast<const float4*>(&A[(size_t)(m0+m)*K + k0 + kq*4]);
            As[kq*4+0][m] = v.x; As[kq*4+1][m] = v.y;
            As[kq*4+2][m] = v.z; As[kq*4+3][m] = v.w;
        }
        // W tile: 64x16 = 256 float4, 1 per thread (guard N)
        {
            int n = tid >> 2, kq = tid & 3;
            float4 v = make_float4(0.f,0.f,0.f,0.f);
            if (n0 + n < N)
                v = *reinterpret_cast<const float4*>(&W[(size_t)(n0+n)*K + k0 + kq*4]);
            Ws[kq*4+0][n] = v.x; Ws[kq*4+1][n] = v.y;
            Ws[kq*4+2][n] = v.z; Ws[kq*4+3][n] = v.w;
        }
        __syncthreads();
#pragma unroll
        for (int kk = 0; kk < GBK; kk++) {
            float a[8], wv[4];
            *reinterpret_cast<float4*>(&a[0]) = *reinterpret_cast<float4*>(&As[kk][ty*8]);
            *reinterpret_cast<float4*>(&a[4]) = *reinterpret_cast<float4*>(&As[kk][ty*8+4]);
            *reinterpret_cast<float4*>(&wv[0]) = *reinterpret_cast<float4*>(&Ws[kk][tx*4]);
#pragma unroll
            for (int i = 0; i < 8; i++)
#pragma unroll
                for (int j = 0; j < 4; j++) acc[i][j] += a[i]*wv[j];
        }
        __syncthreads();
    }
#pragma unroll
    for (int i = 0; i < 8; i++) {
        int row = m0 + ty*8 + i;
#pragma unroll
        for (int j = 0; j < 4; j++) {
            int col = n0 + tx*4 + j;
            if (col < N) C[(size_t)row*N + col] = acc[i][j];
        }
    }
}

// ---------------- causal depthwise conv (k=4) + SiLU ----------------
__global__ void conv_silu_kernel(const float* __restrict__ cw, const float* __restrict__ cb) {
    int idx = blockIdx.x*blockDim.x + threadIdx.x;     // RTOT*D_INNER
    if (idx >= RTOT*D_INNER) return;
    int d = idx & (D_INNER-1);
    int r = idx >> 9;
    int b = r >> 11;
    int t = r & (SEQ-1);
    float acc = cb[d];
#pragma unroll
    for (int j = 0; j < D_CONV; j++) {
        int tt = t - (D_CONV-1) + j;
        if (tt >= 0) acc += cw[d*D_CONV + j] * g_xz[((size_t)((b<<11)+tt))*(2*D_INNER) + d];
    }
    float sg = 1.f/(1.f + __expf(-acc));
    g_xh[idx] = acc * sg;
}

// ---------------- dt = softplus(dbl[:,:16] @ dtW^T + dtb) ----------------
__global__ void dt_kernel(const float* __restrict__ dtW, const float* __restrict__ dtb) {
    int idx = blockIdx.x*blockDim.x + threadIdx.x;     // RTOT*D_INNER
    if (idx >= RTOT*D_INNER) return;
    int d = idx & (D_INNER-1);
    int r = idx >> 9;
    float acc = dtb[d];
    const float* drow = &g_dbl[(size_t)r*XPROJ_N];
#pragma unroll
    for (int k = 0; k < DT_RANK; k++) acc += drow[k] * dtW[d*DT_RANK + k];
    g_dt[idx] = (acc > 20.f) ? acc : log1pf(__expf(acc));
}

// ---------------- chunked scan, pass A: per-chunk products + local states ----------------
__global__ __launch_bounds__(128) void scanA_kernel(const float* __restrict__ A_log) {
    int gid = blockIdx.x;                 // B * NC * 4 = 512 blocks
    int db = gid & 3;
    int c  = (gid >> 2) & (NC-1);
    int b  = gid >> 7;
    int d  = db*128 + threadIdx.x;
    int t0 = c * CHUNK;

    __shared__ float sB[CHUNK][D_STATE];
    for (int i = threadIdx.x; i < CHUNK*D_STATE; i += 128) {
        int t = i >> 4, n = i & 15;
        sB[t][n] = g_dbl[((size_t)(b*SEQ + t0 + t))*XPROJ_N + DT_RANK + n];
    }
    __syncthreads();

    float Areg[D_STATE];
    bool structured = true;
#pragma unroll
    for (int n = 0; n < D_STATE; n++) {
        Areg[n] = -__expf(A_log[d*D_STATE + n]);
        structured = structured && (fabsf(Areg[n] + (float)(n+1)) < 1e-3f*(float)(n+1));
    }

    float hs[D_STATE], P[D_STATE];
#pragma unroll
    for (int n = 0; n < D_STATE; n++) { hs[n] = 0.f; P[n] = 1.f; }

    const float* dtp = &g_dt[(size_t)(b*SEQ + t0)*D_INNER + d];
    const float* xp  = &g_xh[(size_t)(b*SEQ + t0)*D_INNER + d];

    if (structured) {
        for (int t = 0; t < CHUNK; t++) {
            float dt = dtp[(size_t)t*D_INNER];
            float x  = xp [(size_t)t*D_INNER];
            float e = __expf(-dt);
            float s = dt * x;
            float da = e;
#pragma unroll
            for (int n = 0; n < D_STATE; n++) {
                hs[n] = da*hs[n] + s*sB[t][n];
                P[n] *= da;
                da *= e;
            }
        }
    } else {
        for (int t = 0; t < CHUNK; t++) {
            float dt = dtp[(size_t)t*D_INNER];
            float x  = xp [(size_t)t*D_INNER];
            float s = dt * x;
#pragma unroll
            for (int n = 0; n < D_STATE; n++) {
                float da = __expf(dt*Areg[n]);
                hs[n] = da*hs[n] + s*sB[t][n];
                P[n] *= da;
            }
        }
    }

    size_t base = ((size_t)(b*D_INNER + d)*D_STATE)*NC + c;
#pragma unroll
    for (int n = 0; n < D_STATE; n++) {
        g_cP[base + (size_t)n*NC] = P[n];
        g_cH[base + (size_t)n*NC] = hs[n];
    }
}

// ---------------- pass B: serial combine across chunks (tiny) ----------------
__global__ void scanB_kernel() {
    int idx = blockIdx.x*blockDim.x + threadIdx.x;     // B*D_INNER*D_STATE = 32768
    if (idx >= BATCH*D_INNER*D_STATE) return;
    size_t base = (size_t)idx * NC;
    float carry = 0.f;
#pragma unroll 4
    for (int c = 0; c < NC; c++) {
        g_carry[base + c] = carry;
        carry = g_cP[base + c]*carry + g_cH[base + c];
    }
}

// ---------------- pass C: replay with true carry, emit y, fuse D-skip + SiLU gate ----------------
__global__ __launch_bounds__(128) void scanC_kernel(const float* __restrict__ A_log,
                                                    const float* __restrict__ Dp) {
    int gid = blockIdx.x;
    int db = gid & 3;
    int c  = (gid >> 2) & (NC-1);
    int b  = gid >> 7;
    int d  = db*128 + threadIdx.x;
    int t0 = c * CHUNK;

    __shared__ float sB[CHUNK][D_STATE];
    __shared__ float sC[CHUNK][D_STATE];
    for (int i = threadIdx.x; i < CHUNK*D_STATE; i += 128) {
        int t = i >> 4, n = i & 15;
        size_t row = ((size_t)(b*SEQ + t0 + t))*XPROJ_N;
        sB[t][n] = g_dbl[row + DT_RANK + n];
        sC[t][n] = g_dbl[row + DT_RANK + D_STATE + n];
    }
    __syncthreads();

    float Areg[D_STATE];
    bool structured = true;
#pragma unroll
    for (int n = 0; n < D_STATE; n++) {
        Areg[n] = -__expf(A_log[d*D_STATE + n]);
        structured = structured && (fabsf(Areg[n] + (float)(n+1)) < 1e-3f*(float)(n+1));
    }

    float hs[D_STATE];
    size_t base = ((size_t)(b*D_INNER + d)*D_STATE)*NC + c;
#pragma unroll
    for (int n = 0; n < D_STATE; n++) hs[n] = g_carry[base + (size_t)n*NC];

    float Dd = Dp[d];
    const float* dtp = &g_dt[(size_t)(b*SEQ + t0)*D_INNER + d];
    const float* xp  = &g_xh[(size_t)(b*SEQ + t0)*D_INNER + d];
    const float* zp  = &g_xz[(size_t)(b*SEQ + t0)*(2*D_INNER) + D_INNER + d];
    float*       yp  = &g_y [(size_t)(b*SEQ + t0)*D_INNER + d];

    if (structured) {
        for (int t = 0; t < CHUNK; t++) {
            float dt = dtp[(size_t)t*D_INNER];
            float x  = xp [(size_t)t*D_INNER];
            float e = __expf(-dt);
            float s = dt * x;
            float da = e;
            float y = 0.f;
#pragma unroll
            for (int n = 0; n < D_STATE; n++) {
                hs[n] = da*hs[n] + s*sB[t][n];
                y += hs[n]*sC[t][n];
                da *= e;
            }
            y += Dd * x;
            float z = zp[(size_t)t*(2*D_INNER)];
            y *= z / (1.f + __expf(-z));
            yp[(size_t)t*D_INNER] = y;
        }
    } else {
        for (int t = 0; t < CHUNK; t++) {
            float dt = dtp[(size_t)t*D_INNER];
            float x  = xp [(size_t)t*D_INNER];
            float s = dt * x;
            float y = 0.f;
#pragma unroll
            for (int n = 0; n < D_STATE; n++) {
                float da = __expf(dt*Areg[n]);
                hs[n] = da*hs[n] + s*sB[t][n];
                y += hs[n]*sC[t][n];
            }
            y += Dd * x;
            float z = zp[(size_t)t*(2*D_INNER)];
            y *= z / (1.f + __expf(-z));
            yp[(size_t)t*D_INNER] = y;
        }
    }
}

// ---------------- head: out = h @ out_W^T (N=1) ----------------
__global__ void head_kernel(const float* __restrict__ Wout, float* __restrict__ out) {
    int r = blockIdx.x*8 + (threadIdx.x >> 5);
    int lane = threadIdx.x & 31;
    float acc = 0.f;
#pragma unroll
    for (int k = 0; k < 8; k++)
        acc += g_h[(size_t)r*D_MODEL + lane + k*32] * Wout[lane + k*32];
#pragma unroll
    for (int o = 16; o > 0; o >>= 1) acc += __shfl_xor_sync(0xffffffffu, acc, o);
    if (lane == 0) out[r] = acc;
}

// ---------------- driver ----------------
extern "C" void kernel_launch(void* const* d_in, const int* in_sizes, int n_in,
                              void* d_out, int out_size)
{
    const float* x_src  = (const float*)d_in[0];
    // d_in[1] = single_eval_pos (unused by reference)
    const float* in_W   = (const float*)d_in[2];
    const float* norm_w = (const float*)d_in[3];
    const float* norm_b = (const float*)d_in[4];
    const float* inproj = (const float*)d_in[5];
    const float* conv_w = (const float*)d_in[6];
    const float* conv_b = (const float*)d_in[7];
    const float* xproj  = (const float*)d_in[8];
    const float* dtW    = (const float*)d_in[9];
    const float* dtb    = (const float*)d_in[10];
    const float* A_log  = (const float*)d_in[11];
    const float* Dp     = (const float*)d_in[12];
    const float* outproj= (const float*)d_in[13];
    const float* outW   = (const float*)d_in[14];

    float *p_hn, *p_xz, *p_xh, *p_dbl, *p_y, *p_h;
    cudaGetSymbolAddress((void**)&p_hn,  g_hn);
    cudaGetSymbolAddress((void**)&p_xz,  g_xz);
    cudaGetSymbolAddress((void**)&p_xh,  g_xh);
    cudaGetSymbolAddress((void**)&p_dbl, g_dbl);
    cudaGetSymbolAddress((void**)&p_y,   g_y);
    cudaGetSymbolAddress((void**)&p_h,   g_h);

    embed_kernel<<<RTOT, 256>>>(x_src, in_W);

    for (int l = 0; l < N_LAYERS; l++) {
        add_ln_kernel<<<RTOT, 256>>>(norm_w + l*D_MODEL, norm_b + l*D_MODEL, l == 0);

        // in_proj: xz = hn @ inW^T   (M=8192, N=1024, K=256)
        gemm_nt_kernel<<<dim3((2*D_INNER)/GBN, RTOT/GBM), 256>>>(
            p_hn, inproj + (size_t)l*2*D_INNER*D_MODEL, p_xz, RTOT, 2*D_INNER, D_MODEL);

        conv_silu_kernel<<<(RTOT*D_INNER)/256, 256>>>(
            conv_w + (size_t)l*D_INNER*D_CONV, conv_b + l*D_INNER);

        // xproj: dbl = xh @ xpW^T    (M=8192, N=48, K=512)
        gemm_nt_kernel<<<dim3((XPROJ_N + GBN - 1)/GBN, RTOT/GBM), 256>>>(
            p_xh, xproj + (size_t)l*XPROJ_N*D_INNER, p_dbl, RTOT, XPROJ_N, D_INNER);

        dt_kernel<<<(RTOT*D_INNER)/256, 256>>>(
            dtW + (size_t)l*D_INNER*DT_RANK, dtb + l*D_INNER);

        scanA_kernel<<<BATCH*NC*4, 128>>>(A_log + (size_t)l*D_INNER*D_STATE);
        scanB_kernel<<<(BATCH*D_INNER*D_STATE)/256, 256>>>();
        scanC_kernel<<<BATCH*NC*4, 128>>>(A_log + (size_t)l*D_INNER*D_STATE,
                                          Dp + l*D_INNER);

        // out_proj: h = y @ opW^T    (M=8192, N=256, K=512)
        gemm_nt_kernel<<<dim3(D_MODEL/GBN, RTOT/GBM), 256>>>(
            p_y, outproj + (size_t)l*D_MODEL*D_INNER, p_h, RTOT, D_MODEL, D_INNER);
    }

    head_kernel<<<RTOT/8, 256>>>(outW, (float*)d_out);
}

// round 4
// speedup vs baseline: 1.2382x; 1.2382x over previous
#include <cuda_runtime.h>
#include <cuda_bf16.h>
#include <cstdint>
#include <math.h>

#define BATCH 4
#define SEQ 2048
#define RTOT (BATCH*SEQ)        // 8192 rows
#define INPUT_LEN 15
#define D_MODEL 256
#define N_LAYERS 4
#define D_INNER 512
#define D_STATE 16
#define D_CONV 4
#define DT_RANK 16
#define NC 32                   // chunks for parallel scan
#define CHUNK (SEQ/NC)          // 64
#define LN_EPS 1e-5f

// K3 (triplet-expanded K) values
#define K3_IN  (3*D_MODEL)      // 768
#define K3_XO  (3*D_INNER)      // 1536

// ---------------- persistent device scratch (no allocations) ----------------
__device__ float g_h  [RTOT*D_MODEL];
__device__ float g_res[RTOT*D_MODEL];
__device__ float g_xz [RTOT*2*D_INNER];
__device__ float g_xh [RTOT*D_INNER];
__device__ float g_dbl[RTOT*64];          // padded xproj output, stride 64
__device__ float g_dt [RTOT*D_INNER];
__device__ float g_cP   [BATCH*D_INNER*D_STATE*NC];
__device__ float g_cH   [BATCH*D_INNER*D_STATE*NC];
__device__ float g_carry[BATCH*D_INNER*D_STATE*NC];
__device__ __align__(16) __nv_bfloat16 g_a3[RTOT*K3_XO];       // activation triplets
__device__ __align__(16) __nv_bfloat16 g_w3[1024*K3_XO];       // weight triplets

// ---------------- helpers ----------------
__device__ __forceinline__ void cp16(void* smem, const void* g) {
    uint32_t s = (uint32_t)__cvta_generic_to_shared(smem);
    asm volatile("cp.async.cg.shared.global [%0], [%1], 16;" :: "r"(s), "l"(g));
}
#define CP_COMMIT() asm volatile("cp.async.commit_group;" ::: "memory")
#define CP_WAIT(N)  asm volatile("cp.async.wait_group %0;" :: "n"(N) : "memory")

__device__ __forceinline__ void ldm_x4(uint32_t& r0, uint32_t& r1, uint32_t& r2, uint32_t& r3,
                                       const void* p) {
    uint32_t a = (uint32_t)__cvta_generic_to_shared(p);
    asm volatile("ldmatrix.sync.aligned.m8n8.x4.shared.b16 {%0,%1,%2,%3}, [%4];"
                 : "=r"(r0), "=r"(r1), "=r"(r2), "=r"(r3) : "r"(a));
}
__device__ __forceinline__ void mma_bf16(float* c, const uint32_t* a, uint32_t b0, uint32_t b1) {
    asm volatile("mma.sync.aligned.m16n8k16.row.col.f32.bf16.bf16.f32 "
                 "{%0,%1,%2,%3}, {%4,%5,%6,%7}, {%8,%9}, {%0,%1,%2,%3};"
                 : "+f"(c[0]), "+f"(c[1]), "+f"(c[2]), "+f"(c[3])
                 : "r"(a[0]), "r"(a[1]), "r"(a[2]), "r"(a[3]), "r"(b0), "r"(b1));
}

// write fp32 -> (hi, lo, hi) bf16 triplet (activation side)
__device__ __forceinline__ void write_tripA(__nv_bfloat16* dst, float a) {
    __nv_bfloat16 h = __float2bfloat16(a);
    __nv_bfloat16 l = __float2bfloat16(a - __bfloat162float(h));
    dst[0] = h; dst[1] = l; dst[2] = h;
}

// ---------------- embed: h = x_src @ in_W^T ----------------
__global__ void embed_kernel(const float* __restrict__ x, const float* __restrict__ W) {
    __shared__ float xs[INPUT_LEN];
    int r = blockIdx.x;
    int m = threadIdx.x;
    if (m < INPUT_LEN) xs[m] = x[r*INPUT_LEN + m];
    __syncthreads();
    float acc = 0.f;
#pragma unroll
    for (int k = 0; k < INPUT_LEN; k++) acc += xs[k] * W[m*INPUT_LEN + k];
    g_h[r*D_MODEL + m] = acc;
}

// ---------------- residual add + layernorm, writes hn triplet ----------------
__global__ void add_ln_kernel(const float* __restrict__ w, const float* __restrict__ b, int first) {
    int r = blockIdx.x;
    int c = threadIdx.x;
    float v = g_h[r*D_MODEL + c];
    if (!first) v += g_res[r*D_MODEL + c];
    g_res[r*D_MODEL + c] = v;

    float s = v, s2 = v*v;
#pragma unroll
    for (int o = 16; o > 0; o >>= 1) {
        s  += __shfl_xor_sync(0xffffffffu, s,  o);
        s2 += __shfl_xor_sync(0xffffffffu, s2, o);
    }
    __shared__ float ss[8], ss2[8];
    int wid = threadIdx.x >> 5, lane = threadIdx.x & 31;
    if (lane == 0) { ss[wid] = s; ss2[wid] = s2; }
    __syncthreads();
    if (wid == 0) {
        s  = (lane < 8) ? ss[lane]  : 0.f;
        s2 = (lane < 8) ? ss2[lane] : 0.f;
#pragma unroll
        for (int o = 4; o > 0; o >>= 1) {
            s  += __shfl_xor_sync(0xffffffffu, s,  o);
            s2 += __shfl_xor_sync(0xffffffffu, s2, o);
        }
        if (lane == 0) { ss[0] = s; ss2[0] = s2; }
    }
    __syncthreads();
    float mean = ss[0] * (1.0f/D_MODEL);
    float var  = ss2[0] * (1.0f/D_MODEL) - mean*mean;
    float hn = (v - mean) * rsqrtf(var + LN_EPS) * w[c] + b[c];
    write_tripA(&g_a3[(size_t)r*K3_IN + 3*c], hn);
}

// ---------------- weight fp32 [N,K] -> triplet bf16 [Npad,3K] (h,h,l), zero pad ----------------
__global__ void convW_kernel(const float* __restrict__ W, int N, int K, int Npad) {
    int idx = blockIdx.x*256 + threadIdx.x;
    if (idx >= Npad*K) return;
    int n = idx / K, k = idx - n*K;
    float v = (n < N) ? W[(size_t)n*K + k] : 0.f;
    __nv_bfloat16 h = __float2bfloat16(v);
    __nv_bfloat16 l = __float2bfloat16(v - __bfloat162float(h));
    __nv_bfloat16* d = &g_w3[((size_t)n*K + k)*3];
    d[0] = h; d[1] = h; d[2] = l;
}

// ---------------- HMMA GEMM: C[M,N] = A3[M,K3] "*" W3[N,K3]^T ----------------
// BM=128, BK=32, 256 threads = 8 warps (4 M x 2 N). Warp tile 32 x (BN/2).
#define BM 128
#define BK 32
#define PAD 8
#define LDS (BK + PAD)          // 40 bf16 row stride -> conflict-free ldmatrix
template<int BN>
__global__ __launch_bounds__(256) void mma_gemm(
    const __nv_bfloat16* __restrict__ A3, const __nv_bfloat16* __restrict__ B3,
    float* __restrict__ C, int K3, int ldc)
{
    __shared__ __nv_bfloat16 sA[2][BM*LDS];
    __shared__ __nv_bfloat16 sB[2][BN*LDS];

    const int tid = threadIdx.x;
    const int warp = tid >> 5, lane = tid & 31;
    const int m0 = blockIdx.y * BM;
    const int n0 = blockIdx.x * BN;
    const int wm = (warp & 3) * 32;          // warp M offset in tile
    const int wn = (warp >> 2) * (BN/2);     // warp N offset in tile
    constexpr int NT = BN/16;                // n8-tiles per warp = 8 (BN=128) / 4 (BN=64)

    const int S = K3 / BK;

    auto load_stage = [&](int s, int buf) {
        const __nv_bfloat16* Ag = A3 + (size_t)m0*K3 + s*BK;
        int row = tid >> 2, ch = tid & 3;
#pragma unroll
        for (int it = 0; it < 2; it++) {
            int rr = row + it*64;
            cp16(&sA[buf][rr*LDS + ch*8], Ag + (size_t)rr*K3 + ch*8);
        }
        const __nv_bfloat16* Bg = B3 + (size_t)n0*K3 + s*BK;
#pragma unroll
        for (int it = 0; it < BN/64; it++) {
            int rr = row + it*64;
            cp16(&sB[buf][rr*LDS + ch*8], Bg + (size_t)rr*K3 + ch*8);
        }
    };

    float acc[2][NT][4];
#pragma unroll
    for (int mi = 0; mi < 2; mi++)
#pragma unroll
        for (int nj = 0; nj < NT; nj++)
#pragma unroll
            for (int q = 0; q < 4; q++) acc[mi][nj][q] = 0.f;

    load_stage(0, 0); CP_COMMIT();
    load_stage(1, 1); CP_COMMIT();

    const int lrow = lane & 15;              // ldmatrix row within 16
    const int lcol = (lane >> 4) * 8;        // ldmatrix col half

    for (int s = 0; s < S; s++) {
        if (s + 1 < S) { CP_WAIT(1); } else { CP_WAIT(0); }
        __syncthreads();
        int buf = s & 1;
#pragma unroll
        for (int kk = 0; kk < BK; kk += 16) {
            uint32_t a[2][4];
#pragma unroll
            for (int mi = 0; mi < 2; mi++)
                ldm_x4(a[mi][0], a[mi][1], a[mi][2], a[mi][3],
                       &sA[buf][(wm + mi*16 + lrow)*LDS + kk + lcol]);
            uint32_t b[NT][2];
#pragma unroll
            for (int np = 0; np < NT/2; np++) {
                uint32_t r0, r1, r2, r3;
                ldm_x4(r0, r1, r2, r3,
                       &sB[buf][(wn + np*16 + lrow)*LDS + kk + lcol]);
                b[2*np][0] = r0; b[2*np+1][0] = r1;
                b[2*np][1] = r2; b[2*np+1][1] = r3;
            }
#pragma unroll
            for (int mi = 0; mi < 2; mi++)
#pragma unroll
                for (int nj = 0; nj < NT; nj++)
                    mma_bf16(acc[mi][nj], a[mi], b[nj][0], b[nj][1]);
        }
        __syncthreads();
        if (s + 2 < S) { load_stage(s + 2, buf); CP_COMMIT(); }
    }

    // epilogue: direct fp32 stores
    const int gid = lane >> 2, tig = lane & 3;
#pragma unroll
    for (int mi = 0; mi < 2; mi++) {
        int row = m0 + wm + mi*16 + gid;
#pragma unroll
        for (int nj = 0; nj < NT; nj++) {
            int col = n0 + wn + nj*8 + tig*2;
            *reinterpret_cast<float2*>(&C[(size_t)row*ldc + col]) =
                make_float2(acc[mi][nj][0], acc[mi][nj][1]);
            *reinterpret_cast<float2*>(&C[(size_t)(row+8)*ldc + col]) =
                make_float2(acc[mi][nj][2], acc[mi][nj][3]);
        }
    }
}

// ---------------- causal depthwise conv (k=4) + SiLU; writes fp32 + triplet ----------------
__global__ void conv_silu_kernel(const float* __restrict__ cw, const float* __restrict__ cb) {
    int idx = blockIdx.x*blockDim.x + threadIdx.x;     // RTOT*D_INNER
    if (idx >= RTOT*D_INNER) return;
    int d = idx & (D_INNER-1);
    int r = idx >> 9;
    int b = r >> 11;
    int t = r & (SEQ-1);
    float acc = cb[d];
#pragma unroll
    for (int j = 0; j < D_CONV; j++) {
        int tt = t - (D_CONV-1) + j;
        if (tt >= 0) acc += cw[d*D_CONV + j] * g_xz[((size_t)((b<<11)+tt))*(2*D_INNER) + d];
    }
    float sg = 1.f/(1.f + __expf(-acc));
    float xh = acc * sg;
    g_xh[idx] = xh;
    write_tripA(&g_a3[(size_t)r*K3_XO + 3*d], xh);
}

// ---------------- dt = softplus(dbl[:,:16] @ dtW^T + dtb) ----------------
__global__ void dt_kernel(const float* __restrict__ dtW, const float* __restrict__ dtb) {
    int idx = blockIdx.x*blockDim.x + threadIdx.x;     // RTOT*D_INNER
    if (idx >= RTOT*D_INNER) return;
    int d = idx & (D_INNER-1);
    int r = idx >> 9;
    float acc = dtb[d];
    const float* drow = &g_dbl[(size_t)r*64];
#pragma unroll
    for (int k = 0; k < DT_RANK; k++) acc += drow[k] * dtW[d*DT_RANK + k];
    g_dt[idx] = (acc > 20.f) ? acc : log1pf(__expf(acc));
}

// ---------------- chunked scan, pass A ----------------
__global__ __launch_bounds__(128) void scanA_kernel(const float* __restrict__ A_log) {
    int gid = blockIdx.x;                 // B * NC * 4 = 512 blocks
    int db = gid & 3;
    int c  = (gid >> 2) & (NC-1);
    int b  = gid >> 7;
    int d  = db*128 + threadIdx.x;
    int t0 = c * CHUNK;

    __shared__ float sB[CHUNK][D_STATE];
    for (int i = threadIdx.x; i < CHUNK*D_STATE; i += 128) {
        int t = i >> 4, n = i & 15;
        sB[t][n] = g_dbl[((size_t)(b*SEQ + t0 + t))*64 + DT_RANK + n];
    }
    __syncthreads();

    float Areg[D_STATE];
    bool structured = true;
#pragma unroll
    for (int n = 0; n < D_STATE; n++) {
        Areg[n] = -__expf(A_log[d*D_STATE + n]);
        structured = structured && (fabsf(Areg[n] + (float)(n+1)) < 1e-3f*(float)(n+1));
    }

    float hs[D_STATE], P[D_STATE];
#pragma unroll
    for (int n = 0; n < D_STATE; n++) { hs[n] = 0.f; P[n] = 1.f; }

    const float* dtp = &g_dt[(size_t)(b*SEQ + t0)*D_INNER + d];
    const float* xp  = &g_xh[(size_t)(b*SEQ + t0)*D_INNER + d];

    if (structured) {
        for (int t = 0; t < CHUNK; t++) {
            float dt = dtp[(size_t)t*D_INNER];
            float x  = xp [(size_t)t*D_INNER];
            float e = __expf(-dt);
            float s = dt * x;
            float da = e;
#pragma unroll
            for (int n = 0; n < D_STATE; n++) {
                hs[n] = da*hs[n] + s*sB[t][n];
                P[n] *= da;
                da *= e;
            }
        }
    } else {
        for (int t = 0; t < CHUNK; t++) {
            float dt = dtp[(size_t)t*D_INNER];
            float x  = xp [(size_t)t*D_INNER];
            float s = dt * x;
#pragma unroll
            for (int n = 0; n < D_STATE; n++) {
                float da = __expf(dt*Areg[n]);
                hs[n] = da*hs[n] + s*sB[t][n];
                P[n] *= da;
            }
        }
    }

    size_t base = ((size_t)(b*D_INNER + d)*D_STATE)*NC + c;
#pragma unroll
    for (int n = 0; n < D_STATE; n++) {
        g_cP[base + (size_t)n*NC] = P[n];
        g_cH[base + (size_t)n*NC] = hs[n];
    }
}

// ---------------- pass B: serial combine across chunks ----------------
__global__ void scanB_kernel() {
    int idx = blockIdx.x*blockDim.x + threadIdx.x;     // B*D_INNER*D_STATE = 32768
    if (idx >= BATCH*D_INNER*D_STATE) return;
    size_t base = (size_t)idx * NC;
    float carry = 0.f;
#pragma unroll 4
    for (int c = 0; c < NC; c++) {
        g_carry[base + c] = carry;
        carry = g_cP[base + c]*carry + g_cH[base + c];
    }
}

// ---------------- pass C: replay with carry, y -> triplet (fused D-skip + SiLU gate) ----------------
__global__ __launch_bounds__(128) void scanC_kernel(const float* __restrict__ A_log,
                                                    const float* __restrict__ Dp) {
    int gid = blockIdx.x;
    int db = gid & 3;
    int c  = (gid >> 2) & (NC-1);
    int b  = gid >> 7;
    int d  = db*128 + threadIdx.x;
    int t0 = c * CHUNK;

    __shared__ float sB[CHUNK][D_STATE];
    __shared__ float sC[CHUNK][D_STATE];
    for (int i = threadIdx.x; i < CHUNK*D_STATE; i += 128) {
        int t = i >> 4, n = i & 15;
        size_t row = ((size_t)(b*SEQ + t0 + t))*64;
        sB[t][n] = g_dbl[row + DT_RANK + n];
        sC[t][n] = g_dbl[row + DT_RANK + D_STATE + n];
    }
    __syncthreads();

    float Areg[D_STATE];
    bool structured = true;
#pragma unroll
    for (int n = 0; n < D_STATE; n++) {
        Areg[n] = -__expf(A_log[d*D_STATE + n]);
        structured = structured && (fabsf(Areg[n] + (float)(n+1)) < 1e-3f*(float)(n+1));
    }

    float hs[D_STATE];
    size_t base = ((size_t)(b*D_INNER + d)*D_STATE)*NC + c;
#pragma unroll
    for (int n = 0; n < D_STATE; n++) hs[n] = g_carry[base + (size_t)n*NC];

    float Dd = Dp[d];
    const float* dtp = &g_dt[(size_t)(b*SEQ + t0)*D_INNER + d];
    const float* xp  = &g_xh[(size_t)(b*SEQ + t0)*D_INNER + d];
    const float* zp  = &g_xz[(size_t)(b*SEQ + t0)*(2*D_INNER) + D_INNER + d];
    __nv_bfloat16* yp = &g_a3[(size_t)(b*SEQ + t0)*K3_XO + 3*d];

    if (structured) {
        for (int t = 0; t < CHUNK; t++) {
            float dt = dtp[(size_t)t*D_INNER];
            float x  = xp [(size_t)t*D_INNER];
            float e = __expf(-dt);
            float s = dt * x;
            float da = e;
            float y = 0.f;
#pragma unroll
            for (int n = 0; n < D_STATE; n++) {
                hs[n] = da*hs[n] + s*sB[t][n];
                y += hs[n]*sC[t][n];
                da *= e;
            }
            y += Dd * x;
            float z = zp[(size_t)t*(2*D_INNER)];
            y *= z / (1.f + __expf(-z));
            write_tripA(yp + (size_t)t*K3_XO, y);
        }
    } else {
        for (int t = 0; t < CHUNK; t++) {
            float dt = dtp[(size_t)t*D_INNER];
            float x  = xp [(size_t)t*D_INNER];
            float s = dt * x;
            float y = 0.f;
#pragma unroll
            for (int n = 0; n < D_STATE; n++) {
                float da = __expf(dt*Areg[n]);
                hs[n] = da*hs[n] + s*sB[t][n];
                y += hs[n]*sC[t][n];
            }
            y += Dd * x;
            float z = zp[(size_t)t*(2*D_INNER)];
            y *= z / (1.f + __expf(-z));
            write_tripA(yp + (size_t)t*K3_XO, y);
        }
    }
}

// ---------------- head: out = h @ out_W^T (N=1) ----------------
__global__ void head_kernel(const float* __restrict__ Wout, float* __restrict__ out) {
    int r = blockIdx.x*8 + (threadIdx.x >> 5);
    int lane = threadIdx.x & 31;
    float acc = 0.f;
#pragma unroll
    for (int k = 0; k < 8; k++)
        acc += g_h[(size_t)r*D_MODEL + lane + k*32] * Wout[lane + k*32];
#pragma unroll
    for (int o = 16; o > 0; o >>= 1) acc += __shfl_xor_sync(0xffffffffu, acc, o);
    if (lane == 0) out[r] = acc;
}

// ---------------- driver ----------------
extern "C" void kernel_launch(void* const* d_in, const int* in_sizes, int n_in,
                              void* d_out, int out_size)
{
    const float* x_src  = (const float*)d_in[0];
    const float* in_W   = (const float*)d_in[2];
    const float* norm_w = (const float*)d_in[3];
    const float* norm_b = (const float*)d_in[4];
    const float* inproj = (const float*)d_in[5];
    const float* conv_w = (const float*)d_in[6];
    const float* conv_b = (const float*)d_in[7];
    const float* xproj  = (const float*)d_in[8];
    const float* dtW    = (const float*)d_in[9];
    const float* dtb    = (const float*)d_in[10];
    const float* A_log  = (const float*)d_in[11];
    const float* Dp     = (const float*)d_in[12];
    const float* outproj= (const float*)d_in[13];
    const float* outW   = (const float*)d_in[14];

    float *p_xz, *p_dbl, *p_h;
    __nv_bfloat16 *p_a3, *p_w3;
    cudaGetSymbolAddress((void**)&p_xz,  g_xz);
    cudaGetSymbolAddress((void**)&p_dbl, g_dbl);
    cudaGetSymbolAddress((void**)&p_h,   g_h);
    cudaGetSymbolAddress((void**)&p_a3,  g_a3);
    cudaGetSymbolAddress((void**)&p_w3,  g_w3);

    embed_kernel<<<RTOT, 256>>>(x_src, in_W);

    for (int l = 0; l < N_LAYERS; l++) {
        add_ln_kernel<<<RTOT, 256>>>(norm_w + l*D_MODEL, norm_b + l*D_MODEL, l == 0);

        // in_proj: xz = hn @ inW^T   (M=8192, N=1024, K3=768)
        convW_kernel<<<(1024*D_MODEL + 255)/256, 256>>>(
            inproj + (size_t)l*2*D_INNER*D_MODEL, 1024, D_MODEL, 1024);
        mma_gemm<128><<<dim3(1024/128, RTOT/BM), 256>>>(p_a3, p_w3, p_xz, K3_IN, 1024);

        conv_silu_kernel<<<(RTOT*D_INNER)/256, 256>>>(
            conv_w + (size_t)l*D_INNER*D_CONV, conv_b + l*D_INNER);

        // xproj: dbl = xh @ xpW^T    (M=8192, N=48 pad 64, K3=1536)
        convW_kernel<<<(64*D_INNER + 255)/256, 256>>>(
            xproj + (size_t)l*48*D_INNER, 48, D_INNER, 64);
        mma_gemm<64><<<dim3(1, RTOT/BM), 256>>>(p_a3, p_w3, p_dbl, K3_XO, 64);

        dt_kernel<<<(RTOT*D_INNER)/256, 256>>>(
            dtW + (size_t)l*D_INNER*DT_RANK, dtb + l*D_INNER);

        scanA_kernel<<<BATCH*NC*4, 128>>>(A_log + (size_t)l*D_INNER*D_STATE);
        scanB_kernel<<<(BATCH*D_INNER*D_STATE)/256, 256>>>();
        scanC_kernel<<<BATCH*NC*4, 128>>>(A_log + (size_t)l*D_INNER*D_STATE,
                                          Dp + l*D_INNER);

        // out_proj: h = y @ opW^T    (M=8192, N=256, K3=1536)
        convW_kernel<<<(D_MODEL*D_INNER + 255)/256, 256>>>(
            outproj + (size_t)l*D_MODEL*D_INNER, D_MODEL, D_INNER, D_MODEL);
        mma_gemm<128><<<dim3(D_MODEL/128, RTOT/BM), 256>>>(p_a3, p_w3, p_h, K3_XO, D_MODEL);
    }

    head_kernel<<<RTOT/8, 256>>>(outW, (float*)d_out);
}

// round 5
// speedup vs baseline: 1.6915x; 1.3661x over previous
#include <cuda_runtime.h>
#include <cuda_bf16.h>
#include <cstdint>
#include <math.h>

#define BATCH 4
#define SEQ 2048
#define RTOT (BATCH*SEQ)        // 8192 rows
#define INPUT_LEN 15
#define D_MODEL 256
#define N_LAYERS 4
#define D_INNER 512
#define D_STATE 16
#define D_CONV 4
#define DT_RANK 16
#define NC 32
#define CHUNK (SEQ/NC)          // 64
#define LN_EPS 1e-5f

// expanded operands stored as [hi(K) | lo(K)], row stride 2K; logical K3 = 3K
// weight layer offsets in g_w3 (elements)
#define WOFF_IN(l)  ((size_t)(l)*1024*512)
#define WOFF_XP(l)  ((size_t)2097152 + (size_t)(l)*64*1024)
#define WOFF_OP(l)  ((size_t)2359296 + (size_t)(l)*256*1024)

// ---------------- persistent device scratch ----------------
__device__ float g_h  [RTOT*D_MODEL];
__device__ float g_res[RTOT*D_MODEL];
__device__ float g_xz [RTOT*2*D_INNER];
__device__ float g_xh [RTOT*D_INNER];
__device__ float g_dbl[RTOT*64];
__device__ float g_dt [RTOT*D_INNER];
__device__ float g_cP   [BATCH*D_INNER*D_STATE*NC];
__device__ float g_cH   [BATCH*D_INNER*D_STATE*NC];
__device__ float g_carry[BATCH*D_INNER*D_STATE*NC];
__device__ __align__(16) __nv_bfloat16 g_a3[RTOT*1024];   // activations [hi|lo], max stride 1024
__device__ __align__(16) __nv_bfloat16 g_w3[3407872];     // all layers' weights [hi|lo]

// ---------------- helpers ----------------
__device__ __forceinline__ void cp16(void* smem, const void* g) {
    uint32_t s = (uint32_t)__cvta_generic_to_shared(smem);
    asm volatile("cp.async.cg.shared.global [%0], [%1], 16;" :: "r"(s), "l"(g));
}
#define CP_COMMIT() asm volatile("cp.async.commit_group;" ::: "memory")
#define CP_WAIT(N)  asm volatile("cp.async.wait_group %0;" :: "n"(N) : "memory")

__device__ __forceinline__ void ldm_x4(uint32_t& r0, uint32_t& r1, uint32_t& r2, uint32_t& r3,
                                       const void* p) {
    uint32_t a = (uint32_t)__cvta_generic_to_shared(p);
    asm volatile("ldmatrix.sync.aligned.m8n8.x4.shared.b16 {%0,%1,%2,%3}, [%4];"
                 : "=r"(r0), "=r"(r1), "=r"(r2), "=r"(r3) : "r"(a));
}
__device__ __forceinline__ void mma_bf16(float* c, const uint32_t* a, uint32_t b0, uint32_t b1) {
    asm volatile("mma.sync.aligned.m16n8k16.row.col.f32.bf16.bf16.f32 "
                 "{%0,%1,%2,%3}, {%4,%5,%6,%7}, {%8,%9}, {%0,%1,%2,%3};"
                 : "+f"(c[0]), "+f"(c[1]), "+f"(c[2]), "+f"(c[3])
                 : "r"(a[0]), "r"(a[1]), "r"(a[2]), "r"(a[3]), "r"(b0), "r"(b1));
}
// split fp32 into (hi, lo) bf16
__device__ __forceinline__ void split_bf16(float a, __nv_bfloat16& h, __nv_bfloat16& l) {
    h = __float2bfloat16(a);
    l = __float2bfloat16(a - __bfloat162float(h));
}

// ---------------- embed ----------------
__global__ void embed_kernel(const float* __restrict__ x, const float* __restrict__ W) {
    __shared__ float xs[INPUT_LEN];
    int r = blockIdx.x, m = threadIdx.x;
    if (m < INPUT_LEN) xs[m] = x[r*INPUT_LEN + m];
    __syncthreads();
    float acc = 0.f;
#pragma unroll
    for (int k = 0; k < INPUT_LEN; k++) acc += xs[k] * W[m*INPUT_LEN + k];
    g_h[r*D_MODEL + m] = acc;
}

// ---------------- residual add + LN -> a3 [hi|lo], stride 512 ----------------
__global__ void add_ln_kernel(const float* __restrict__ w, const float* __restrict__ b, int first) {
    int r = blockIdx.x, c = threadIdx.x;
    float v = g_h[r*D_MODEL + c];
    if (!first) v += g_res[r*D_MODEL + c];
    g_res[r*D_MODEL + c] = v;

    float s = v, s2 = v*v;
#pragma unroll
    for (int o = 16; o > 0; o >>= 1) {
        s  += __shfl_xor_sync(0xffffffffu, s,  o);
        s2 += __shfl_xor_sync(0xffffffffu, s2, o);
    }
    __shared__ float ss[8], ss2[8];
    int wid = threadIdx.x >> 5, lane = threadIdx.x & 31;
    if (lane == 0) { ss[wid] = s; ss2[wid] = s2; }
    __syncthreads();
    if (wid == 0) {
        s  = (lane < 8) ? ss[lane]  : 0.f;
        s2 = (lane < 8) ? ss2[lane] : 0.f;
#pragma unroll
        for (int o = 4; o > 0; o >>= 1) {
            s  += __shfl_xor_sync(0xffffffffu, s,  o);
            s2 += __shfl_xor_sync(0xffffffffu, s2, o);
        }
        if (lane == 0) { ss[0] = s; ss2[0] = s2; }
    }
    __syncthreads();
    float mean = ss[0] * (1.0f/D_MODEL);
    float var  = ss2[0] * (1.0f/D_MODEL) - mean*mean;
    float hn = (v - mean) * rsqrtf(var + LN_EPS) * w[c] + b[c];
    __nv_bfloat16 h, l; split_bf16(hn, h, l);
    g_a3[(size_t)r*512 + c]       = h;
    g_a3[(size_t)r*512 + 256 + c] = l;
}

// ---------------- weight conversion (all layers once): fp32 [N,K] -> [hi|lo] stride 2K ----------------
__global__ void convW_kernel(const float* __restrict__ W, __nv_bfloat16* __restrict__ dst,
                             int N, int K, int Npad, size_t srcStride, size_t dstStride) {
    int l = blockIdx.y;
    int idx = blockIdx.x*256 + threadIdx.x;
    if (idx >= Npad*K) return;
    int n = idx / K, k = idx - n*K;
    float v = (n < N) ? W[l*srcStride + (size_t)n*K + k] : 0.f;
    __nv_bfloat16 h, lo; split_bf16(v, h, lo);
    __nv_bfloat16* d = dst + l*dstStride + (size_t)n*(2*K);
    d[k]     = h;
    d[K + k] = lo;
}

// ---------------- HMMA GEMM: C[M,N] = A[M,K3] "*" W[N,K3]^T via K-expansion ----------------
// A regions: 0->hi,1->lo,2->hi ; B regions: 0->hi,1->hi,2->lo (both stored [hi|lo], stride 2K)
#define BK 32
#define PAD 8
#define LDSV (BK + PAD)          // 40
template<int BMT, int BN>
__global__ __launch_bounds__(256) void mma_gemm(
    const __nv_bfloat16* __restrict__ A2, const __nv_bfloat16* __restrict__ B2,
    float* __restrict__ C, int K, int ldc)
{
    extern __shared__ __nv_bfloat16 smem[];
    __nv_bfloat16* sA = smem;                      // [3][BMT*LDSV]
    __nv_bfloat16* sB = smem + 3*BMT*LDSV;         // [3][BN*LDSV]

    constexpr int MW = BMT/32;          // warps along M
    constexpr int NW = 8/MW;            // warps along N
    constexpr int WN = BN/NW;           // N per warp
    constexpr int NT = WN/8;            // n8 tiles per warp

    const int tid = threadIdx.x;
    const int warp = tid >> 5, lane = tid & 31;
    const int m0 = blockIdx.y * BMT;
    const int n0 = blockIdx.x * BN;
    const int wm = (warp % MW) * 32;
    const int wn = (warp / MW) * WN;
    const int S = (3*K)/BK;

    auto load_stage = [&](int s, int buf) {
        int k3 = s*BK;
        int rg = k3 / K, off = k3 - rg*K;
        int srcA = (rg == 1) ? K + off : off;
        int srcB = (rg == 2) ? K + off : off;
        const __nv_bfloat16* Ag = A2 + (size_t)m0*(2*K) + srcA;
        int row = tid >> 2, ch = tid & 3;
        __nv_bfloat16* dA = sA + buf*(BMT*LDSV);
#pragma unroll
        for (int it = 0; it < BMT/64; it++) {
            int rr = row + it*64;
            cp16(&dA[rr*LDSV + ch*8], Ag + (size_t)rr*(2*K) + ch*8);
        }
        const __nv_bfloat16* Bg = B2 + (size_t)n0*(2*K) + srcB;
        __nv_bfloat16* dB = sB + buf*(BN*LDSV);
#pragma unroll
        for (int it = 0; it < BN/64; it++) {
            int rr = row + it*64;
            cp16(&dB[rr*LDSV + ch*8], Bg + (size_t)rr*(2*K) + ch*8);
        }
    };

    float acc[2][NT][4];
#pragma unroll
    for (int mi = 0; mi < 2; mi++)
#pragma unroll
        for (int nj = 0; nj < NT; nj++)
#pragma unroll
            for (int q = 0; q < 4; q++) acc[mi][nj][q] = 0.f;

    load_stage(0, 0); CP_COMMIT();
    load_stage(1, 1); CP_COMMIT();

    const int lrow = lane & 15;
    const int lcol = (lane >> 4) * 8;

    for (int s = 0; s < S; s++) {
        if (s + 1 < S) { CP_WAIT(1); } else { CP_WAIT(0); }
        __syncthreads();
        if (s + 2 < S) { load_stage(s + 2, (s + 2) % 3); CP_COMMIT(); }
        int buf = s % 3;
        const __nv_bfloat16* cA = sA + buf*(BMT*LDSV);
        const __nv_bfloat16* cB = sB + buf*(BN*LDSV);
#pragma unroll
        for (int kk = 0; kk < BK; kk += 16) {
            uint32_t a[2][4];
#pragma unroll
            for (int mi = 0; mi < 2; mi++)
                ldm_x4(a[mi][0], a[mi][1], a[mi][2], a[mi][3],
                       &cA[(wm + mi*16 + lrow)*LDSV + kk + lcol]);
            uint32_t b[NT][2];
#pragma unroll
            for (int np = 0; np < NT/2; np++) {
                uint32_t r0, r1, r2, r3;
                ldm_x4(r0, r1, r2, r3, &cB[(wn + np*16 + lrow)*LDSV + kk + lcol]);
                b[2*np][0] = r0; b[2*np+1][0] = r1;
                b[2*np][1] = r2; b[2*np+1][1] = r3;
            }
#pragma unroll
            for (int mi = 0; mi < 2; mi++)
#pragma unroll
                for (int nj = 0; nj < NT; nj++)
                    mma_bf16(acc[mi][nj], a[mi], b[nj][0], b[nj][1]);
        }
    }

    const int gid = lane >> 2, tig = lane & 3;
#pragma unroll
    for (int mi = 0; mi < 2; mi++) {
        int row = m0 + wm + mi*16 + gid;
#pragma unroll
        for (int nj = 0; nj < NT; nj++) {
            int col = n0 + wn + nj*8 + tig*2;
            *reinterpret_cast<float2*>(&C[(size_t)row*ldc + col]) =
                make_float2(acc[mi][nj][0], acc[mi][nj][1]);
            *reinterpret_cast<float2*>(&C[(size_t)(row+8)*ldc + col]) =
                make_float2(acc[mi][nj][2], acc[mi][nj][3]);
        }
    }
}

// ---------------- causal conv (k=4) + SiLU, 4 timesteps per thread ----------------
__global__ void conv_silu_kernel(const float* __restrict__ cw, const float* __restrict__ cb) {
    int idx = blockIdx.x*256 + threadIdx.x;          // RTOT*D_INNER/4
    if (idx >= RTOT*D_INNER/4) return;
    int d  = idx & (D_INNER-1);
    int rq = idx >> 9;
    int b  = rq >> 9;                                 // 512 groups per batch
    int t0 = (rq & 511) * 4;

    float w0 = cw[d*4+0], w1 = cw[d*4+1], w2 = cw[d*4+2], w3 = cw[d*4+3];
    float bias = cb[d];
    float xin[7];
#pragma unroll
    for (int j = 0; j < 7; j++) {
        int tt = t0 - 3 + j;
        xin[j] = (tt >= 0) ? g_xz[((size_t)((b<<11) + tt))*(2*D_INNER) + d] : 0.f;
    }
#pragma unroll
    for (int q = 0; q < 4; q++) {
        float acc = bias + w0*xin[q] + w1*xin[q+1] + w2*xin[q+2] + w3*xin[q+3];
        float xh = acc / (1.f + __expf(-acc));
        int r = (b<<11) + t0 + q;
        g_xh[(size_t)r*D_INNER + d] = xh;
        __nv_bfloat16 h, l; split_bf16(xh, h, l);
        g_a3[(size_t)r*1024 + d]       = h;
        g_a3[(size_t)r*1024 + 512 + d] = l;
    }
}

// ---------------- scan pass A: fused dt + per-chunk products/local states ----------------
__global__ __launch_bounds__(128) void scanA_kernel(const float* __restrict__ A_log,
                                                    const float* __restrict__ dtW,
                                                    const float* __restrict__ dtb) {
    int gid = blockIdx.x;                 // B*NC*4
    int db = gid & 3;
    int c  = (gid >> 2) & (NC-1);
    int b  = gid >> 7;
    int d  = db*128 + threadIdx.x;
    int t0 = c * CHUNK;

    __shared__ float sD[CHUNK][DT_RANK];
    __shared__ float sB[CHUNK][D_STATE];
    for (int i = threadIdx.x; i < CHUNK*D_STATE; i += 128) {
        int t = i >> 4, n = i & 15;
        size_t row = ((size_t)(b*SEQ + t0 + t))*64;
        sD[t][n] = g_dbl[row + n];
        sB[t][n] = g_dbl[row + DT_RANK + n];
    }
    __syncthreads();

    float wdt[DT_RANK];
#pragma unroll
    for (int k = 0; k < DT_RANK; k++) wdt[k] = dtW[d*DT_RANK + k];
    float bias = dtb[d];

    float Areg[D_STATE];
    bool structured = true;
#pragma unroll
    for (int n = 0; n < D_STATE; n++) {
        Areg[n] = -__expf(A_log[d*D_STATE + n]);
        structured = structured && (fabsf(Areg[n] + (float)(n+1)) < 1e-3f*(float)(n+1));
    }

    float hs[D_STATE], P[D_STATE];
#pragma unroll
    for (int n = 0; n < D_STATE; n++) { hs[n] = 0.f; P[n] = 1.f; }

    const float* xp = &g_xh[(size_t)(b*SEQ + t0)*D_INNER + d];
    float*      dtp = &g_dt[(size_t)(b*SEQ + t0)*D_INNER + d];

    for (int t = 0; t < CHUNK; t++) {
        float lin = bias;
#pragma unroll
        for (int k = 0; k < DT_RANK; k++) lin += wdt[k]*sD[t][k];
        float dt = (lin > 20.f) ? lin : log1pf(__expf(lin));
        dtp[(size_t)t*D_INNER] = dt;
        float x = xp[(size_t)t*D_INNER];
        float s = dt * x;
        if (structured) {
            float e = __expf(-dt);
            float da = e;
#pragma unroll
            for (int n = 0; n < D_STATE; n++) {
                hs[n] = da*hs[n] + s*sB[t][n];
                P[n] *= da;
                da *= e;
            }
        } else {
#pragma unroll
            for (int n = 0; n < D_STATE; n++) {
                float da = __expf(dt*Areg[n]);
                hs[n] = da*hs[n] + s*sB[t][n];
                P[n] *= da;
            }
        }
    }

    size_t base = ((size_t)(b*D_INNER + d)*D_STATE)*NC + c;
#pragma unroll
    for (int n = 0; n < D_STATE; n++) {
        g_cP[base + (size_t)n*NC] = P[n];
        g_cH[base + (size_t)n*NC] = hs[n];
    }
}

// ---------------- scan pass B ----------------
__global__ void scanB_kernel() {
    int idx = blockIdx.x*blockDim.x + threadIdx.x;
    if (idx >= BATCH*D_INNER*D_STATE) return;
    size_t base = (size_t)idx * NC;
    float carry = 0.f;
#pragma unroll 4
    for (int c = 0; c < NC; c++) {
        g_carry[base + c] = carry;
        carry = g_cP[base + c]*carry + g_cH[base + c];
    }
}

// ---------------- scan pass C: replay + D-skip + SiLU gate -> a3 [hi|lo] stride 1024 ----------------
__global__ __launch_bounds__(128) void scanC_kernel(const float* __restrict__ A_log,
                                                    const float* __restrict__ Dp) {
    int gid = blockIdx.x;
    int db = gid & 3;
    int c  = (gid >> 2) & (NC-1);
    int b  = gid >> 7;
    int d  = db*128 + threadIdx.x;
    int t0 = c * CHUNK;

    __shared__ float sB[CHUNK][D_STATE];
    __shared__ float sC[CHUNK][D_STATE];
    for (int i = threadIdx.x; i < CHUNK*D_STATE; i += 128) {
        int t = i >> 4, n = i & 15;
        size_t row = ((size_t)(b*SEQ + t0 + t))*64;
        sB[t][n] = g_dbl[row + DT_RANK + n];
        sC[t][n] = g_dbl[row + DT_RANK + D_STATE + n];
    }
    __syncthreads();

    float Areg[D_STATE];
    bool structured = true;
#pragma unroll
    for (int n = 0; n < D_STATE; n++) {
        Areg[n] = -__expf(A_log[d*D_STATE + n]);
        structured = structured && (fabsf(Areg[n] + (float)(n+1)) < 1e-3f*(float)(n+1));
    }

    float hs[D_STATE];
    size_t base = ((size_t)(b*D_INNER + d)*D_STATE)*NC + c;
#pragma unroll
    for (int n = 0; n < D_STATE; n++) hs[n] = g_carry[base + (size_t)n*NC];

    float Dd = Dp[d];
    const float* dtp = &g_dt[(size_t)(b*SEQ + t0)*D_INNER + d];
    const float* xp  = &g_xh[(size_t)(b*SEQ + t0)*D_INNER + d];
    const float* zp  = &g_xz[(size_t)(b*SEQ + t0)*(2*D_INNER) + D_INNER + d];
    __nv_bfloat16* yp = &g_a3[(size_t)(b*SEQ + t0)*1024 + d];

    for (int t = 0; t < CHUNK; t++) {
        float dt = dtp[(size_t)t*D_INNER];
        float x  = xp [(size_t)t*D_INNER];
        float s = dt * x;
        float y = 0.f;
        if (structured) {
            float e = __expf(-dt);
            float da = e;
#pragma unroll
            for (int n = 0; n < D_STATE; n++) {
                hs[n] = da*hs[n] + s*sB[t][n];
                y += hs[n]*sC[t][n];
                da *= e;
            }
        } else {
#pragma unroll
            for (int n = 0; n < D_STATE; n++) {
                float da = __expf(dt*Areg[n]);
                hs[n] = da*hs[n] + s*sB[t][n];
                y += hs[n]*sC[t][n];
            }
        }
        y += Dd * x;
        float z = zp[(size_t)t*(2*D_INNER)];
        y *= z / (1.f + __expf(-z));
        __nv_bfloat16 h, l; split_bf16(y, h, l);
        yp[(size_t)t*1024]       = h;
        yp[(size_t)t*1024 + 512] = l;
    }
}

// ---------------- head ----------------
__global__ void head_kernel(const float* __restrict__ Wout, float* __restrict__ out) {
    int r = blockIdx.x*8 + (threadIdx.x >> 5);
    int lane = threadIdx.x & 31;
    float acc = 0.f;
#pragma unroll
    for (int k = 0; k < 8; k++)
        acc += g_h[(size_t)r*D_MODEL + lane + k*32] * Wout[lane + k*32];
#pragma unroll
    for (int o = 16; o > 0; o >>= 1) acc += __shfl_xor_sync(0xffffffffu, acc, o);
    if (lane == 0) out[r] = acc;
}

// ---------------- driver ----------------
extern "C" void kernel_launch(void* const* d_in, const int* in_sizes, int n_in,
                              void* d_out, int out_size)
{
    const float* x_src  = (const float*)d_in[0];
    const float* in_W   = (const float*)d_in[2];
    const float* norm_w = (const float*)d_in[3];
    const float* norm_b = (const float*)d_in[4];
    const float* inproj = (const float*)d_in[5];
    const float* conv_w = (const float*)d_in[6];
    const float* conv_b = (const float*)d_in[7];
    const float* xproj  = (const float*)d_in[8];
    const float* dtW    = (const float*)d_in[9];
    const float* dtb    = (const float*)d_in[10];
    const float* A_log  = (const float*)d_in[11];
    const float* Dp     = (const float*)d_in[12];
    const float* outproj= (const float*)d_in[13];
    const float* outW   = (const float*)d_in[14];

    float *p_xz, *p_dbl, *p_h;
    __nv_bfloat16 *p_a3, *p_w3;
    cudaGetSymbolAddress((void**)&p_xz,  g_xz);
    cudaGetSymbolAddress((void**)&p_dbl, g_dbl);
    cudaGetSymbolAddress((void**)&p_h,   g_h);
    cudaGetSymbolAddress((void**)&p_a3,  g_a3);
    cudaGetSymbolAddress((void**)&p_w3,  g_w3);

    const int SM_128_128 = 3*(128+128)*LDSV*2;   // 61440
    const int SM_64_128  = 3*(64+128)*LDSV*2;    // 46080
    const int SM_64_64   = 3*(64+64)*LDSV*2;     // 30720
    cudaFuncSetAttribute(mma_gemm<128,128>, cudaFuncAttributeMaxDynamicSharedMemorySize, SM_128_128);
    cudaFuncSetAttribute(mma_gemm<64,128>,  cudaFuncAttributeMaxDynamicSharedMemorySize, SM_64_128);
    cudaFuncSetAttribute(mma_gemm<64,64>,   cudaFuncAttributeMaxDynamicSharedMemorySize, SM_64_64);

    // convert all weights once (3 launches)
    convW_kernel<<<dim3(1024, N_LAYERS), 256>>>(inproj,  p_w3 + WOFF_IN(0), 1024, 256, 1024,
                                                (size_t)1024*256, (size_t)1024*512);
    convW_kernel<<<dim3(128,  N_LAYERS), 256>>>(xproj,   p_w3 + WOFF_XP(0), 48, 512, 64,
                                                (size_t)48*512, (size_t)64*1024);
    convW_kernel<<<dim3(512,  N_LAYERS), 256>>>(outproj, p_w3 + WOFF_OP(0), 256, 512, 256,
                                                (size_t)256*512, (size_t)256*1024);

    embed_kernel<<<RTOT, 256>>>(x_src, in_W);

    for (int l = 0; l < N_LAYERS; l++) {
        add_ln_kernel<<<RTOT, 256>>>(norm_w + l*D_MODEL, norm_b + l*D_MODEL, l == 0);

        // in_proj: (M=8192, N=1024, K=256)
        mma_gemm<128,128><<<dim3(8, 64), 256, SM_128_128>>>(
            p_a3, p_w3 + WOFF_IN(l), p_xz, 256, 1024);

        conv_silu_kernel<<<(RTOT*D_INNER/4 + 255)/256, 256>>>(
            conv_w + (size_t)l*D_INNER*D_CONV, conv_b + l*D_INNER);

        // xproj: (M=8192, N=64, K=512)
        mma_gemm<64,64><<<dim3(1, 128), 256, SM_64_64>>>(
            p_a3, p_w3 + WOFF_XP(l), p_dbl, 512, 64);

        scanA_kernel<<<BATCH*NC*4, 128>>>(A_log + (size_t)l*D_INNER*D_STATE,
                                          dtW + (size_t)l*D_INNER*DT_RANK,
                                          dtb + l*D_INNER);
        scanB_kernel<<<(BATCH*D_INNER*D_STATE)/256, 256>>>();
        scanC_kernel<<<BATCH*NC*4, 128>>>(A_log + (size_t)l*D_INNER*D_STATE,
                                          Dp + l*D_INNER);

        // out_proj: (M=8192, N=256, K=512)
        mma_gemm<64,128><<<dim3(2, 128), 256, SM_64_128>>>(
            p_a3, p_w3 + WOFF_OP(l), p_h, 512, 256);
    }

    head_kernel<<<RTOT/8, 256>>>(outW, (float*)d_out);
}